// round 4
// baseline (speedup 1.0000x reference)
#include <cuda_runtime.h>
#include <cuda_bf16.h>
#include <cstdint>

// eeg_input [16, 32, 1000, 64] fp32 -> per (b,w) slab: 64x1000 transpose of 1000x64.
//   out[bw][c*1000 + t] = in[bw][t*64 + c]
// Tail (out_size - PATCH_ELEMS == 640, f32): channel = i/5, time = i%5, i in [0,320).

#define N_BW   512
#define T_DIM  1000
#define C_DIM  64
#define PATCH_ELEMS (N_BW * T_DIM * C_DIM)   // 32,768,000 floats

#define TT 256   // time-tile (rows)
// Tile: 32 channels x 256 time steps per CTA, 256 threads.
// smem padded to 33 floats per t-row -> both scalar smem phases conflict-free.

__global__ __launch_bounds__(256) void labram_transpose_fused_kernel(
    const float* __restrict__ in, float* __restrict__ out, int tail_mode)
{
    __shared__ float tile[TT][33];

    const int bw    = blockIdx.z;
    const int tBase = blockIdx.y * TT;
    const int cBase = blockIdx.x * 32;

    const float* __restrict__ inp  = in  + (size_t)bw * (T_DIM * C_DIM);
    float*       __restrict__ outp = out + (size_t)bw * (T_DIM * C_DIM);

    const int tid = threadIdx.x;

    // ---- Load phase: float4 along c, 8 independent front-batched LDG.128 ----
    const int cq = tid & 7;    // float4 column within 32-c tile (0..7)
    const int tr = tid >> 3;   // local t row (0..31), rounds add +32

    float4 v[8];
    bool   p[8];
    #pragma unroll
    for (int j = 0; j < 8; ++j) {
        const int t = tBase + tr + 32 * j;
        p[j] = (t < T_DIM);
        if (p[j]) {
            v[j] = *reinterpret_cast<const float4*>(inp + t * C_DIM + cBase + 4 * cq);
        }
    }
    #pragma unroll
    for (int j = 0; j < 8; ++j) {
        if (p[j]) {
            const int lt = tr + 32 * j;
            tile[lt][4 * cq + 0] = v[j].x;
            tile[lt][4 * cq + 1] = v[j].y;
            tile[lt][4 * cq + 2] = v[j].z;
            tile[lt][4 * cq + 3] = v[j].w;
        }
    }
    __syncthreads();

    // ---- Store phase: float4 along t, 8 STG.128 per thread ----
    const int c  = tid >> 3;   // local channel (0..31)
    const int tq = tid & 7;    // t-quad index within round

    const int cRow = (cBase + c) * T_DIM;
    #pragma unroll
    for (int r = 0; r < 8; ++r) {
        const int ltb = 4 * (tq + 8 * r);    // local t base (0..252, step 4)
        const int t   = tBase + ltb;
        if (t + 3 < T_DIM) {
            float4 o;
            o.x = tile[ltb + 0][c];
            o.y = tile[ltb + 1][c];
            o.z = tile[ltb + 2][c];
            o.w = tile[ltb + 3][c];
            *reinterpret_cast<float4*>(outp + cRow + t) = o;
        }
    }

    // ---- Fused index tail (one CTA only) ----
    if (tail_mode != 0 && blockIdx.x == 0 && blockIdx.y == 0 && blockIdx.z == 0) {
        for (int i = tid; i < 320; i += 256) {
            if (tail_mode == 1) {            // float32-encoded indices
                out[PATCH_ELEMS + i]       = (float)(i / 5);
                out[PATCH_ELEMS + 320 + i] = (float)(i % 5);
            } else {                          // raw int64 indices
                long long* t64 = (long long*)(out + PATCH_ELEMS);
                t64[i]       = (long long)(i / 5);
                t64[320 + i] = (long long)(i % 5);
            }
        }
    }
}

extern "C" void kernel_launch(void* const* d_in, const int* in_sizes, int n_in,
                              void* d_out, int out_size)
{
    const float* eeg = (const float*)d_in[0];
    float* out = (float*)d_out;

    const long long tail = (long long)out_size - (long long)PATCH_ELEMS;
    int tail_mode = 0;
    if (tail == 1280)     tail_mode = 2;   // int64 tail
    else if (tail >= 640) tail_mode = 1;   // float32 tail (observed case)

    dim3 block(256);
    dim3 grid(C_DIM / 32,                    // 2 channel tiles
              (T_DIM + TT - 1) / TT,         // 4 time tiles (last partial: 232)
              N_BW);                         // 512 batches
    labram_transpose_fused_kernel<<<grid, block>>>(eeg, out, tail_mode);
}

// round 9
// speedup vs baseline: 1.1997x; 1.1997x over previous
#include <cuda_runtime.h>
#include <cuda_bf16.h>
#include <cstdint>

// eeg_input [16, 32, 1000, 64] fp32 -> per (b,w) slab: 64x1000 transpose of 1000x64.
//   out[bw][c*1000 + t] = in[bw][t*64 + c]
// Tail (out_size - PATCH_ELEMS == 640, f32): channel = i/5, time = i%5, i in [0,320).

#define N_BW   512
#define T_DIM  1000
#define C_DIM  64
#define PATCH_ELEMS (N_BW * T_DIM * C_DIM)   // 32,768,000 floats

#define TT  64   // time rows per CTA (full 64-channel width)
#define PAD 65   // smem row stride in floats (scalar access only)

// Tile: 64 t-rows x 64 channels per CTA, 256 threads, smem 16.64KB, 8 CTAs/SM.
// Load mapping gives 128B-contiguous global segments per 8 lanes AND
// conflict-free scalar STS (bank = tl + 4*mlow + k, bijective per warp).
__global__ __launch_bounds__(256, 8) void labram_transpose_fused_kernel(
    const float* __restrict__ in, float* __restrict__ out, int tail_mode)
{
    __shared__ float tile[TT * PAD];

    const int bw    = blockIdx.z;
    const int tBase = blockIdx.y * TT;

    const float* __restrict__ inp  = in  + (size_t)bw * (T_DIM * C_DIM);
    float*       __restrict__ outp = out + (size_t)bw * (T_DIM * C_DIM);

    const int tid = threadIdx.x;

    // ---- Load phase: 4 front-batched LDG.128 over the 64x16-quad grid ----
    float4 v[4];
    bool   p[4];
    int    tl[4], m[4];
    #pragma unroll
    for (int j = 0; j < 4; ++j) {
        const int idx  = tid + 256 * j;      // 0..1023 quad index
        const int half = idx >> 9;           // row half: quads 0-7 vs 8-15
        tl[j] = (idx >> 3) & 63;             // local t row
        m[j]  = (idx & 7) + 8 * half;        // quad within row (0..15)
        const int t = tBase + tl[j];
        p[j] = (t < T_DIM);
        if (p[j]) {
            v[j] = __ldcs(reinterpret_cast<const float4*>(
                              inp + t * C_DIM + 4 * m[j]));
        }
    }
    // Scalar STS (16B alignment not required; banks conflict-free).
    #pragma unroll
    for (int j = 0; j < 4; ++j) {
        if (p[j]) {
            const int base = tl[j] * PAD + 4 * m[j];
            tile[base + 0] = v[j].x;
            tile[base + 1] = v[j].y;
            tile[base + 2] = v[j].z;
            tile[base + 3] = v[j].w;
        }
    }
    __syncthreads();

    // ---- Store phase: 4 STG.128 per thread, conflict-free scalar LDS ----
    const int cl = tid >> 3;   // local channel (0..31)
    const int tq = tid & 7;    // t-quad index

    #pragma unroll
    for (int h = 0; h < 2; ++h) {                 // channel halves
        const int c = 32 * h + cl;
        const size_t cRow = (size_t)c * T_DIM;
        #pragma unroll
        for (int r = 0; r < 2; ++r) {
            const int lt = 4 * tq + 32 * r;       // local t base (step 4)
            const int t  = tBase + lt;
            if (t + 3 < T_DIM) {
                float4 o;
                o.x = tile[(lt + 0) * PAD + c];
                o.y = tile[(lt + 1) * PAD + c];
                o.z = tile[(lt + 2) * PAD + c];
                o.w = tile[(lt + 3) * PAD + c];
                __stcs(reinterpret_cast<float4*>(outp + cRow + t), o);
            }
        }
    }

    // ---- Fused index tail (one CTA only) ----
    if (tail_mode != 0 && blockIdx.y == 0 && blockIdx.z == 0) {
        for (int i = tid; i < 320; i += 256) {
            if (tail_mode == 1) {            // float32-encoded indices
                out[PATCH_ELEMS + i]       = (float)(i / 5);
                out[PATCH_ELEMS + 320 + i] = (float)(i % 5);
            } else {                          // raw int64 indices
                long long* t64 = (long long*)(out + PATCH_ELEMS);
                t64[i]       = (long long)(i / 5);
                t64[320 + i] = (long long)(i % 5);
            }
        }
    }
}

extern "C" void kernel_launch(void* const* d_in, const int* in_sizes, int n_in,
                              void* d_out, int out_size)
{
    const float* eeg = (const float*)d_in[0];
    float* out = (float*)d_out;

    const long long tail = (long long)out_size - (long long)PATCH_ELEMS;
    int tail_mode = 0;
    if (tail == 1280)     tail_mode = 2;   // int64 tail
    else if (tail >= 640) tail_mode = 1;   // float32 tail (observed case)

    dim3 block(256);
    dim3 grid(1,
              (T_DIM + TT - 1) / TT,   // 16 time tiles (last partial: 40 rows)
              N_BW);                   // 512 batches
    labram_transpose_fused_kernel<<<grid, block>>>(eeg, out, tail_mode);
}